// round 2
// baseline (speedup 1.0000x reference)
#include <cuda_runtime.h>
#include <cuda_bf16.h>
#include <cstdint>

// Sparsemax over rows of [B=2048, V=32000] fp32.
// Streaming 2-pass design, one CTA (512 thr) per row, 3 CTAs/SM:
//   pass 1: stream row, compute max + collect candidate SUPERSET
//           (x >= warp_running_max - 1.001  is provably a superset of the
//            true sparsemax support {x >= rowmax - 1})
//   Michelot's algorithm on candidates -> exact tau
//   pass 2: re-stream row (L2-resident: 3*148 rows = 57MB < 126MB L2),
//           emit max(x - tau, 0)

#define THREADS 512
#define VROW    32000
#define V4ROW   8000
#define ITERS   16          // ceil(8000 / 512)
#define CAP     8192        // candidate buffer (32KB smem); expected use ~800
#define NEG_INF (-3.4e38f)
#define SLACK   1.001f

__global__ __launch_bounds__(THREADS, 3)
void sparsemax_kernel(const float* __restrict__ in, float* __restrict__ out)
{
    __shared__ float cand[CAP];
    __shared__ float s_red[16];
    __shared__ float s_max;
    __shared__ float s_tau;
    __shared__ int   s_num;
    __shared__ float s_fsum;
    __shared__ int   s_fcnt;

    const int tid  = threadIdx.x;
    const int lane = tid & 31;
    const int wid  = tid >> 5;
    const unsigned FULL = 0xffffffffu;
    const unsigned lmask_lt = (1u << lane) - 1u;

    const size_t row_off = (size_t)blockIdx.x * VROW;
    const float4* __restrict__ inrow  = (const float4*)(in  + row_off);
    float4*       __restrict__ outrow = (float4*)(out + row_off);

    if (tid == 0) s_num = 0;
    __syncthreads();

    // ================= pass 1: max + candidate superset =================
    float rm = NEG_INF;   // warp-shared running max (uniform across warp)
#pragma unroll
    for (int it = 0; it < ITERS; ++it) {
        int idx = tid + it * THREADS;
        float4 v;
        if (idx < V4ROW) v = inrow[idx];
        else             v = make_float4(NEG_INF, NEG_INF, NEG_INF, NEG_INF);

        float m4 = fmaxf(fmaxf(v.x, v.y), fmaxf(v.z, v.w));
        float wm = m4;
#pragma unroll
        for (int off = 16; off; off >>= 1)
            wm = fmaxf(wm, __shfl_xor_sync(FULL, wm, off));
        rm = fmaxf(rm, wm);
        const float th = rm - SLACK;   // rm <= rowmax  =>  superset condition

        float c[4] = {v.x, v.y, v.z, v.w};
#pragma unroll
        for (int j = 0; j < 4; ++j) {
            float x = c[j];
            bool p = (x >= th);
            unsigned m = __ballot_sync(FULL, p);
            if (m) {
                int leader = __ffs(m) - 1;
                int base = 0;
                if (lane == leader) base = atomicAdd(&s_num, __popc(m));
                base = __shfl_sync(FULL, base, leader);
                if (p) {
                    int pos = base + __popc(m & lmask_lt);
                    if (pos < CAP) cand[pos] = x;
                }
            }
        }
    }

    // block max (rm is warp-uniform)
    if (lane == 0) s_red[wid] = rm;
    __syncthreads();
    if (wid == 0) {
        float m = (lane < 16) ? s_red[lane] : NEG_INF;
#pragma unroll
        for (int off = 16; off; off >>= 1)
            m = fmaxf(m, __shfl_xor_sync(FULL, m, off));
        if (lane == 0) s_max = m;
    }
    __syncthreads();

    const float rmax = s_max;
    const bool ovf = (s_num > CAP);

    // ================= Michelot's algorithm (exact tau) =================
    if (!ovf) {
        if (wid == 0) {
            const int n = s_num;
            float t = -2.0f;     // below tau* (tau* in (-1.001, 0])
            int prev = -1;
            for (int itc = 0; itc < n + 2; ++itc) {
                float sum = 0.0f;
                int cnt = 0;
                for (int i = lane; i < n; i += 32) {
                    float y = cand[i] - rmax;   // shifted: in [-..., 0]
                    if (y > t) { sum += y; cnt++; }
                }
#pragma unroll
                for (int off = 16; off; off >>= 1) {
                    sum += __shfl_xor_sync(FULL, sum, off);
                    cnt += __shfl_xor_sync(FULL, cnt, off);
                }
                if (cnt == prev) break;  // active set stable -> fixed point
                prev = cnt;
                t = (sum - 1.0f) / (float)cnt;
            }
            if (lane == 0) s_tau = t;
        }
    } else {
        // never expected for this data; exact block-wide Michelot over the
        // full row (row still in L2) for unconditional correctness.
        float t = -2.0f;
        int prev = -1;
        for (int iter = 0; iter < VROW; ++iter) {
            if (tid == 0) { s_fsum = 0.0f; s_fcnt = 0; }
            __syncthreads();
            float sum = 0.0f;
            int cnt = 0;
            for (int it = 0; it < ITERS; ++it) {
                int idx = tid + it * THREADS;
                if (idx < V4ROW) {
                    float4 v = inrow[idx];
                    float c[4] = {v.x, v.y, v.z, v.w};
#pragma unroll
                    for (int j = 0; j < 4; ++j) {
                        float y = c[j] - rmax;
                        if (y > t) { sum += y; cnt++; }
                    }
                }
            }
#pragma unroll
            for (int off = 16; off; off >>= 1) {
                sum += __shfl_xor_sync(FULL, sum, off);
                cnt += __shfl_xor_sync(FULL, cnt, off);
            }
            if (lane == 0) { atomicAdd(&s_fsum, sum); atomicAdd(&s_fcnt, cnt); }
            __syncthreads();
            int c = s_fcnt;
            float fs = s_fsum;
            __syncthreads();
            if (c == prev) break;
            prev = c;
            t = (fs - 1.0f) / (float)c;
        }
        if (tid == 0) s_tau = t;
    }
    __syncthreads();

    const float tau = rmax + s_tau;

    // ================= pass 2: emit (row re-read hits L2) ===============
#pragma unroll
    for (int it = 0; it < ITERS; ++it) {
        int idx = tid + it * THREADS;
        if (idx < V4ROW) {
            float4 v = __ldcs(&inrow[idx]);
            float4 r;
            r.x = fmaxf(v.x - tau, 0.0f);
            r.y = fmaxf(v.y - tau, 0.0f);
            r.z = fmaxf(v.z - tau, 0.0f);
            r.w = fmaxf(v.w - tau, 0.0f);
            __stcs(&outrow[idx], r);
        }
    }
}

extern "C" void kernel_launch(void* const* d_in, const int* in_sizes, int n_in,
                              void* d_out, int out_size)
{
    const float* in = (const float*)d_in[0];
    float* out = (float*)d_out;
    int B = out_size / VROW;
    sparsemax_kernel<<<B, THREADS>>>(in, out);
}

// round 3
// speedup vs baseline: 1.1042x; 1.1042x over previous
#include <cuda_runtime.h>
#include <cuda_bf16.h>
#include <cstdint>

// Sparsemax over rows of [B=2048, V=32000] fp32.
// Persistent producer/consumer CTAs, 2 per SM.
//  - producer warp: cp.async.bulk quarter-row chunks into 3-buffer smem ring
//  - 16 consumer warps: single smem scan -> max + candidate superset
//    (threshold = warp running max - 1.001, superset of true support)
//  - Michelot on candidates (exact tau)
//  - store pass: re-read row via L2 (__ldcg), write __stcs

#define VROW        32000
#define V4ROW       8000
#define CHUNK_F4    2000
#define CHUNK_BYTES 32000
#define NCHUNK      4
#define NBUF        3
#define THREADS     544
#define CONS        512
#define CWARPS      16
#define CAP         4096
#define SLACK       1.001f
#define NEG_INF     (-3.4e38f)

// dynamic smem layout (bytes)
#define OFF_BUF    0
#define OFF_CAND   (NBUF * CHUNK_BYTES)          // 96000
#define OFF_RED    (OFF_CAND + CAP * 4)          // 112384
#define OFF_NUM    (OFF_RED + CWARPS * 4)        // 112448
#define OFF_TAU    (OFF_NUM + 4)                 // 112452
#define OFF_MBAR   (OFF_NUM + 16)                // 112464 (8-aligned)
#define SMEM_TOTAL (OFF_MBAR + 2 * NBUF * 8)     // 112512

__device__ __forceinline__ uint32_t smem_u32(const void* p) {
    return (uint32_t)__cvta_generic_to_shared(p);
}
__device__ __forceinline__ void mbar_init(uint32_t a, uint32_t cnt) {
    asm volatile("mbarrier.init.shared.b64 [%0], %1;" :: "r"(a), "r"(cnt) : "memory");
}
__device__ __forceinline__ void mbar_arrive(uint32_t a) {
    asm volatile("mbarrier.arrive.shared.b64 _, [%0];" :: "r"(a) : "memory");
}
__device__ __forceinline__ void mbar_arrive_tx(uint32_t a, uint32_t tx) {
    asm volatile("mbarrier.arrive.expect_tx.shared.b64 _, [%0], %1;"
                 :: "r"(a), "r"(tx) : "memory");
}
__device__ __forceinline__ void mbar_wait(uint32_t a, uint32_t parity) {
    asm volatile(
        "{\n\t"
        ".reg .pred P1;\n\t"
        "WAIT_LOOP_%=:\n\t"
        "mbarrier.try_wait.parity.acquire.cta.shared::cta.b64 P1, [%0], %1, 0x989680;\n\t"
        "@P1 bra.uni WAIT_DONE_%=;\n\t"
        "bra.uni WAIT_LOOP_%=;\n\t"
        "WAIT_DONE_%=:\n\t"
        "}"
        :: "r"(a), "r"(parity) : "memory");
}
__device__ __forceinline__ void bulk_g2s(uint32_t dst, const void* src,
                                         uint32_t bytes, uint32_t mbar) {
    asm volatile(
        "cp.async.bulk.shared::cta.global.mbarrier::complete_tx::bytes [%0], [%1], %2, [%3];"
        :: "r"(dst), "l"(src), "r"(bytes), "r"(mbar) : "memory");
}
__device__ __forceinline__ void cons_bar() {
    asm volatile("bar.sync 1, 512;" ::: "memory");
}

__global__ __launch_bounds__(THREADS, 2)
void sparsemax_kernel(const float* __restrict__ in, float* __restrict__ out, int B)
{
    extern __shared__ char smem[];
    float* cand  = (float*)(smem + OFF_CAND);
    float* s_red = (float*)(smem + OFF_RED);
    int*   s_num = (int*)  (smem + OFF_NUM);
    float* s_tau = (float*)(smem + OFF_TAU);
    const uint32_t mb = smem_u32(smem + OFF_MBAR);

    const int tid  = threadIdx.x;
    const int lane = tid & 31;
    const int wid  = tid >> 5;
    const int G    = gridDim.x;
    const unsigned FULL = 0xffffffffu;

    if (tid == 0) {
        *s_num = 0;
        for (int b = 0; b < NBUF; ++b) {
            mbar_init(mb + b * 16,     1);        // full: producer tx
            mbar_init(mb + b * 16 + 8, CWARPS);   // empty: 16 consumer warps
        }
    }
    __syncthreads();

    // ===================== producer =====================
    if (tid >= CONS) {
        if (tid == CONS) {
            int q = 0;
            for (int row = blockIdx.x; row < B; row += G) {
                const char* rp = (const char*)(in + (size_t)row * VROW);
                for (int k = 0; k < NCHUNK; ++k) {
                    int b  = q % NBUF;
                    int ph = ((q / NBUF) & 1) ^ 1;   // first pass succeeds
                    mbar_wait(mb + b * 16 + 8, ph);
                    mbar_arrive_tx(mb + b * 16, CHUNK_BYTES);
                    bulk_g2s(smem_u32(smem + OFF_BUF + b * CHUNK_BYTES),
                             rp + (size_t)k * CHUNK_BYTES, CHUNK_BYTES,
                             mb + b * 16);
                    ++q;
                }
            }
        }
        return;
    }

    // ===================== consumers =====================
    int q = 0;
    for (int row = blockIdx.x; row < B; row += G) {
        float wm = NEG_INF;   // warp running max (warp-uniform after shuffles)

        for (int k = 0; k < NCHUNK; ++k) {
            int b  = q % NBUF;
            int ph = (q / NBUF) & 1;
            mbar_wait(mb + b * 16, ph);
            const float4* cb = (const float4*)(smem + OFF_BUF + b * CHUNK_BYTES);

            float4 u[4];
            float tm = NEG_INF;
#pragma unroll
            for (int j = 0; j < 4; ++j) {
                int idx = tid + j * CONS;
                if (j < 3 || idx < CHUNK_F4) {
                    u[j] = cb[idx];
                    tm = fmaxf(tm, fmaxf(fmaxf(u[j].x, u[j].y), fmaxf(u[j].z, u[j].w)));
                } else {
                    u[j] = make_float4(NEG_INF, NEG_INF, NEG_INF, NEG_INF);
                }
            }
#pragma unroll
            for (int o = 16; o; o >>= 1)
                tm = fmaxf(tm, __shfl_xor_sync(FULL, tm, o));
            wm = fmaxf(wm, tm);
            const float th = wm - SLACK;   // wm <= rowmax -> superset condition

            int c = 0;
#pragma unroll
            for (int j = 0; j < 4; ++j)
                c += (u[j].x >= th) + (u[j].y >= th) + (u[j].z >= th) + (u[j].w >= th);
            if (c) {
                int base = atomicAdd(s_num, c);
#pragma unroll
                for (int j = 0; j < 4; ++j) {
                    float a4[4] = {u[j].x, u[j].y, u[j].z, u[j].w};
#pragma unroll
                    for (int e = 0; e < 4; ++e)
                        if (a4[e] >= th) { if (base < CAP) cand[base] = a4[e]; ++base; }
                }
            }
            __syncwarp();
            if (lane == 0) mbar_arrive(mb + b * 16 + 8);   // release buffer
            ++q;
        }

        if (lane == 0) s_red[wid] = wm;
        cons_bar();   // all candidates + warp maxes in

        if (wid == 0) {
            float m = (lane < CWARPS) ? s_red[lane] : NEG_INF;
#pragma unroll
            for (int o = 16; o; o >>= 1)
                m = fmaxf(m, __shfl_xor_sync(FULL, m, o));
            const float rmax = m;
            const int n = *s_num;
            float t = -2.0f;          // below tau* (tau* in (rmax-1-eps, rmax] shifted)
            if (n <= CAP) {
                int prev = -1;
                for (int itc = 0; itc < n + 2; ++itc) {
                    float sum = 0.0f; int cnt = 0;
                    for (int i = lane; i < n; i += 32) {
                        float y = cand[i] - rmax;
                        if (y > t) { sum += y; cnt++; }
                    }
#pragma unroll
                    for (int o = 16; o; o >>= 1) {
                        sum += __shfl_xor_sync(FULL, sum, o);
                        cnt += __shfl_xor_sync(FULL, cnt, o);
                    }
                    if (cnt == prev) break;    // fixed point -> exact tau
                    prev = cnt;
                    t = (sum - 1.0f) / (float)cnt;
                }
            } else {
                // overflow fallback (never expected): exact Michelot over the
                // full row from global memory, warp 0 only.
                const float* rp = in + (size_t)row * VROW;
                int prev = -1;
                for (int itc = 0; itc < VROW; ++itc) {
                    float sum = 0.0f; int cnt = 0;
                    for (int i = lane; i < VROW; i += 32) {
                        float y = rp[i] - rmax;
                        if (y > t) { sum += y; cnt++; }
                    }
#pragma unroll
                    for (int o = 16; o; o >>= 1) {
                        sum += __shfl_xor_sync(FULL, sum, o);
                        cnt += __shfl_xor_sync(FULL, cnt, o);
                    }
                    if (cnt == prev) break;
                    prev = cnt;
                    t = (sum - 1.0f) / (float)cnt;
                }
            }
            if (lane == 0) { *s_tau = rmax + t; *s_num = 0; }  // reset for next row
        }
        cons_bar();   // tau ready

        const float tau = *s_tau;
        const float4* ir   = (const float4*)(in  + (size_t)row * VROW);
        float4*       orow = (float4*)      (out + (size_t)row * VROW);
#pragma unroll 4
        for (int i = tid; i < V4ROW; i += CONS) {
            float4 v = __ldcg(&ir[i]);      // L2-resident re-read
            float4 r;
            r.x = fmaxf(v.x - tau, 0.0f);
            r.y = fmaxf(v.y - tau, 0.0f);
            r.z = fmaxf(v.z - tau, 0.0f);
            r.w = fmaxf(v.w - tau, 0.0f);
            __stcs(&orow[i], r);
        }
    }
}

extern "C" void kernel_launch(void* const* d_in, const int* in_sizes, int n_in,
                              void* d_out, int out_size)
{
    const float* in = (const float*)d_in[0];
    float* out = (float*)d_out;
    const int B = out_size / VROW;

    int sms = 148;
    cudaDeviceGetAttribute(&sms, cudaDevAttrMultiProcessorCount, 0);
    int G = 2 * sms;
    if (G > B) G = B;

    cudaFuncSetAttribute(sparsemax_kernel,
                         cudaFuncAttributeMaxDynamicSharedMemorySize, SMEM_TOTAL);
    sparsemax_kernel<<<G, THREADS, SMEM_TOTAL>>>(in, out, B);
}

// round 4
// speedup vs baseline: 1.2685x; 1.1489x over previous
#include <cuda_runtime.h>
#include <cuda_bf16.h>
#include <cstdint>

// Sparsemax over rows of [B=2048, V=32000] fp32.
// Persistent CTAs (1/SM, 1024 thr), one row at a time held fully in registers
// (8 x float4 per thread). Software-pipelined: next row's loads are issued
// interleaved with current row's stores, so DRAM stays busy across the
// per-row reduce/Michelot bubble.
//   1) exact block max (register FMAX chain + tree reduce)
//   2) compact candidates {x >= rmax - 1.0009} (superset of true support,
//      since tau* >= rmax - 1) via per-thread count + single atomicAdd
//   3) Michelot fixed-point iteration on candidates -> exact tau
//   4) emit max(x - tau, 0) from registers; load next row into same regs

#define THREADS    1024
#define NWARP      32
#define VROW       32000
#define V4ROW      8000
#define PER_THREAD 8
#define CAP        6144
#define NEG_INF    (-3.4e38f)
#define SLACK      1.0009f

__global__ __launch_bounds__(THREADS, 1)
void sparsemax_kernel(const float* __restrict__ in, float* __restrict__ out, int B)
{
    __shared__ float cand[CAP];
    __shared__ float s_red[NWARP];
    __shared__ float s_max;
    __shared__ float s_tau;
    __shared__ int   s_num;

    const int tid  = threadIdx.x;
    const int lane = tid & 31;
    const int wid  = tid >> 5;
    const int G    = gridDim.x;
    const unsigned FULL = 0xffffffffu;

    if (tid == 0) s_num = 0;

    int row = blockIdx.x;
    if (row >= B) return;

    // ---- preload first row ----
    float4 v[PER_THREAD];
    {
        const float4* ir = (const float4*)(in + (size_t)row * VROW);
#pragma unroll
        for (int i = 0; i < PER_THREAD; ++i) {
            int idx = tid + i * THREADS;
            if (i < PER_THREAD - 1 || idx < V4ROW) v[i] = __ldcs(&ir[idx]);
            else v[i] = make_float4(NEG_INF, NEG_INF, NEG_INF, NEG_INF);
        }
    }

    while (row < B) {
        // ---- exact block max ----
        float tm = NEG_INF;
#pragma unroll
        for (int i = 0; i < PER_THREAD; ++i)
            tm = fmaxf(tm, fmaxf(fmaxf(v[i].x, v[i].y), fmaxf(v[i].z, v[i].w)));
#pragma unroll
        for (int o = 16; o; o >>= 1)
            tm = fmaxf(tm, __shfl_xor_sync(FULL, tm, o));
        if (lane == 0) s_red[wid] = tm;
        __syncthreads();
        if (wid == 0) {
            float m = s_red[lane];
#pragma unroll
            for (int o = 16; o; o >>= 1)
                m = fmaxf(m, __shfl_xor_sync(FULL, m, o));
            if (lane == 0) s_max = m;
        }
        __syncthreads();

        const float rmax = s_max;
        const float th = rmax - SLACK;   // tau* >= rmax-1  =>  superset

        // ---- compact candidates (per-thread count, one atomicAdd) ----
        int c = 0;
#pragma unroll
        for (int i = 0; i < PER_THREAD; ++i)
            c += (v[i].x >= th) + (v[i].y >= th) + (v[i].z >= th) + (v[i].w >= th);
        if (c) {
            int base = atomicAdd(&s_num, c);
#pragma unroll
            for (int i = 0; i < PER_THREAD; ++i) {
                float a4[4] = {v[i].x, v[i].y, v[i].z, v[i].w};
#pragma unroll
                for (int e = 0; e < 4; ++e)
                    if (a4[e] >= th) { if (base < CAP) cand[base] = a4[e]; ++base; }
            }
        }
        __syncthreads();

        // ---- Michelot (warp 0): exact tau fixed point ----
        if (wid == 0) {
            const int n = s_num;
            float t = -2.0f;          // shifted domain: candidates-rmax in [-1.0009, 0]
            if (n <= CAP) {
                int prev = -1;
                for (int itc = 0; itc < n + 2; ++itc) {
                    float sum = 0.0f; int cnt = 0;
                    for (int i = lane; i < n; i += 32) {
                        float y = cand[i] - rmax;
                        if (y > t) { sum += y; cnt++; }
                    }
#pragma unroll
                    for (int o = 16; o; o >>= 1) {
                        sum += __shfl_xor_sync(FULL, sum, o);
                        cnt += __shfl_xor_sync(FULL, cnt, o);
                    }
                    if (cnt == prev) break;   // active set stable -> exact tau
                    prev = cnt;
                    t = (sum - 1.0f) / (float)cnt;
                }
            } else {
                // overflow fallback (degenerate inputs only): exact Michelot
                // over the full row from global memory.
                const float* rp = in + (size_t)row * VROW;
                int prev = -1;
                for (int itc = 0; itc < VROW; ++itc) {
                    float sum = 0.0f; int cnt = 0;
                    for (int i = lane; i < VROW; i += 32) {
                        float y = __ldg(&rp[i]) - rmax;
                        if (y > t) { sum += y; cnt++; }
                    }
#pragma unroll
                    for (int o = 16; o; o >>= 1) {
                        sum += __shfl_xor_sync(FULL, sum, o);
                        cnt += __shfl_xor_sync(FULL, cnt, o);
                    }
                    if (cnt == prev) break;
                    prev = cnt;
                    t = (sum - 1.0f) / (float)cnt;
                }
            }
            if (lane == 0) { s_tau = rmax + t; s_num = 0; }  // reset for next row
        }
        __syncthreads();

        const float tau = s_tau;

        // ---- store current row; interleave loads of the next row ----
        const int nrow = row + G;
        const bool more = (nrow < B);
        float4* orow = (float4*)(out + (size_t)row * VROW);
        const float4* nir = (const float4*)(in + (size_t)(more ? nrow : row) * VROW);

#pragma unroll
        for (int i = 0; i < PER_THREAD; ++i) {
            int idx = tid + i * THREADS;
            bool valid = (i < PER_THREAD - 1) || (idx < V4ROW);
            if (valid) {
                float4 r;
                r.x = fmaxf(v[i].x - tau, 0.0f);
                r.y = fmaxf(v[i].y - tau, 0.0f);
                r.z = fmaxf(v[i].z - tau, 0.0f);
                r.w = fmaxf(v[i].w - tau, 0.0f);
                __stcs(&orow[idx], r);
                if (more) v[i] = __ldcs(&nir[idx]);   // prefetch next row
                else      v[i] = make_float4(NEG_INF, NEG_INF, NEG_INF, NEG_INF);
            } else {
                v[i] = make_float4(NEG_INF, NEG_INF, NEG_INF, NEG_INF);
            }
        }
        row = nrow;
    }
}

extern "C" void kernel_launch(void* const* d_in, const int* in_sizes, int n_in,
                              void* d_out, int out_size)
{
    const float* in = (const float*)d_in[0];
    float* out = (float*)d_out;
    const int B = out_size / VROW;

    int sms = 148;
    cudaDeviceGetAttribute(&sms, cudaDevAttrMultiProcessorCount, 0);
    int G = sms;
    if (G > B) G = B;

    sparsemax_kernel<<<G, THREADS>>>(in, out, B);
}